// round 2
// baseline (speedup 1.0000x reference)
#include <cuda_runtime.h>
#include <cuda_bf16.h>

#define B     16384
#define D     1024
#define N_PER 8
#define G     (B / N_PER)      // 2048
#define MARGIN 0.5f
#define N_PAIRS 28.0f          // 8*7/2

// Scratch (device globals allowed). g_count is zero-initialized at load and
// reset to 0 by the last block each run -> graph-replay safe.
__device__ float        g_group_loss[G];
__device__ unsigned int g_count = 0;

// One block per group. 256 threads; each thread owns one float4 of each of
// the 8 rows. The last block to finish also reduces all group losses.
__global__ __launch_bounds__(256) void fused_kernel(const float* __restrict__ emb,
                                                    float* __restrict__ out) {
    const int g    = blockIdx.x;
    const int tid  = threadIdx.x;
    const int lane = tid & 31;
    const int warp = tid >> 5;

    const float4* base = reinterpret_cast<const float4*>(emb + (size_t)g * N_PER * D);
    float4 v[N_PER];
    float  sq[N_PER];

#pragma unroll
    for (int r = 0; r < N_PER; r++) {
        v[r] = __ldcs(base + r * (D / 4) + tid);   // streaming: read-once data
        sq[r] = v[r].x * v[r].x + v[r].y * v[r].y + v[r].z * v[r].z + v[r].w * v[r].w;
    }

    // Warp-reduce each per-row sum of squares
#pragma unroll
    for (int r = 0; r < N_PER; r++) {
#pragma unroll
        for (int off = 16; off > 0; off >>= 1)
            sq[r] += __shfl_down_sync(0xFFFFFFFFu, sq[r], off);
    }

    __shared__ float s_sq[8][N_PER];
    if (lane == 0) {
#pragma unroll
        for (int r = 0; r < N_PER; r++) s_sq[warp][r] = sq[r];
    }
    __syncthreads();

    __shared__ float s_inv[N_PER];
    if (tid < N_PER) {
        float s = 0.0f;
#pragma unroll
        for (int w = 0; w < 8; w++) s += s_sq[w][tid];
        // rows are unit-scale gaussians: s ~ D, never near 0; rsqrtf is safe
        s_inv[tid] = rsqrtf(fmaxf(s, 1e-24f));
    }
    __syncthreads();

    float sx = 0.f, sy = 0.f, sz = 0.f, sw = 0.f;
#pragma unroll
    for (int r = 0; r < N_PER; r++) {
        const float inv = s_inv[r];
        sx = fmaf(v[r].x, inv, sx);
        sy = fmaf(v[r].y, inv, sy);
        sz = fmaf(v[r].z, inv, sz);
        sw = fmaf(v[r].w, inv, sw);
    }
    float part = sx * sx + sy * sy + sz * sz + sw * sw;

#pragma unroll
    for (int off = 16; off > 0; off >>= 1)
        part += __shfl_down_sync(0xFFFFFFFFu, part, off);

    __shared__ float s_part[8];
    if (lane == 0) s_part[warp] = part;
    __syncthreads();

    __shared__ bool s_last;
    if (tid == 0) {
        float ss = 0.0f;
#pragma unroll
        for (int w = 0; w < 8; w++) ss += s_part[w];
        float mean_intra = 1.0f - (ss - (float)N_PER) / (2.0f * N_PAIRS);
        g_group_loss[g] = fmaxf(mean_intra - MARGIN, 0.0f);
        __threadfence();                         // make the store visible chip-wide
        unsigned int done = atomicAdd(&g_count, 1u);
        s_last = (done == (unsigned)(G - 1));
    }
    __syncthreads();

    if (s_last) {
        // This block saw all G-1 other results (fence + atomic ordering).
        float acc = 0.0f;
#pragma unroll
        for (int i = tid; i < G; i += 256) acc += g_group_loss[i];

#pragma unroll
        for (int off = 16; off > 0; off >>= 1)
            acc += __shfl_down_sync(0xFFFFFFFFu, acc, off);

        __shared__ float s_fin[8];
        if (lane == 0) s_fin[warp] = acc;
        __syncthreads();

        if (tid == 0) {
            float s = 0.0f;
#pragma unroll
            for (int w = 0; w < 8; w++) s += s_fin[w];
            out[0] = s / (float)G;
            g_count = 0;                         // reset for next graph replay
        }
    }
}

extern "C" void kernel_launch(void* const* d_in, const int* in_sizes, int n_in,
                              void* d_out, int out_size) {
    const float* emb = (const float*)d_in[0];
    // d_in[1] = labels (arange(B)//8): grouping is implicit in block->row map
    float* out = (float*)d_out;
    fused_kernel<<<G, 256>>>(emb, out);
}

// round 3
// speedup vs baseline: 1.0170x; 1.0170x over previous
#include <cuda_runtime.h>
#include <cuda_bf16.h>

#define B      16384
#define D      1024
#define DV     (D / 4)         // 256 float4 per row
#define N_PER  8
#define G      (B / N_PER)     // 2048
#define MARGIN 0.5f
#define N_PAIRS 28.0f          // 8*7/2

// Scratch (device globals allowed). g_count zero-init at load, reset by the
// last block each run -> graph-replay safe.
__device__ float        g_group_loss[G];
__device__ unsigned int g_count = 0;

// One block per group. The group's 8x1024 fp32 tile (32 KB) is staged in
// shared memory via cp.async (no register residency, L1 bypass).
__global__ __launch_bounds__(256, 6) void fused_kernel(const float* __restrict__ emb,
                                                       float* __restrict__ out) {
    __shared__ float4 s_rows[N_PER * DV];   // 32 KB
    __shared__ float  s_inv[N_PER];
    __shared__ float  s_red[8];
    __shared__ bool   s_last;

    const int g    = blockIdx.x;
    const int tid  = threadIdx.x;
    const int lane = tid & 31;
    const int warp = tid >> 5;

    // ---- stage tile: each thread cp.asyncs one float4 per row ----
    const float4* base = reinterpret_cast<const float4*>(emb) + (size_t)g * N_PER * DV;
    unsigned int sbase = (unsigned int)__cvta_generic_to_shared(s_rows);
#pragma unroll
    for (int r = 0; r < N_PER; r++) {
        const float4* src = base + r * DV + tid;
        unsigned int  dst = sbase + (unsigned int)(r * DV + tid) * 16u;
        asm volatile("cp.async.cg.shared.global [%0], [%1], 16;\n" :: "r"(dst), "l"(src));
    }
    asm volatile("cp.async.commit_group;\n");
    asm volatile("cp.async.wait_group 0;\n");
    __syncthreads();

    // ---- phase 1: warp w computes inverse L2 norm of row w ----
    {
        const int r = warp;
        float s = 0.0f;
#pragma unroll
        for (int k = 0; k < 8; k++) {
            float4 a = s_rows[r * DV + k * 32 + lane];
            s += a.x * a.x + a.y * a.y + a.z * a.z + a.w * a.w;
        }
#pragma unroll
        for (int off = 16; off > 0; off >>= 1)
            s += __shfl_xor_sync(0xFFFFFFFFu, s, off);
        if (lane == 0) s_inv[r] = rsqrtf(fmaxf(s, 1e-24f));
    }
    __syncthreads();

    // ---- phase 2: group-sum vector component, then ||s||^2 block-reduce ----
    float sx = 0.f, sy = 0.f, sz = 0.f, sw = 0.f;
#pragma unroll
    for (int r = 0; r < N_PER; r++) {
        float4 a = s_rows[r * DV + tid];
        const float inv = s_inv[r];
        sx = fmaf(a.x, inv, sx);
        sy = fmaf(a.y, inv, sy);
        sz = fmaf(a.z, inv, sz);
        sw = fmaf(a.w, inv, sw);
    }
    float part = sx * sx + sy * sy + sz * sz + sw * sw;

#pragma unroll
    for (int off = 16; off > 0; off >>= 1)
        part += __shfl_xor_sync(0xFFFFFFFFu, part, off);
    if (lane == 0) s_red[warp] = part;
    __syncthreads();

    if (tid == 0) {
        float ss = 0.0f;
#pragma unroll
        for (int w = 0; w < 8; w++) ss += s_red[w];
        float mean_intra = 1.0f - (ss - (float)N_PER) / (2.0f * N_PAIRS);
        g_group_loss[g] = fmaxf(mean_intra - MARGIN, 0.0f);
        __threadfence();
        unsigned int done = atomicAdd(&g_count, 1u);
        s_last = (done == (unsigned)(G - 1));
    }
    __syncthreads();

    // ---- last block: deterministic 2048 -> 1 reduction ----
    if (s_last) {
        float acc = 0.0f;
#pragma unroll
        for (int i = tid; i < G; i += 256) acc += g_group_loss[i];
#pragma unroll
        for (int off = 16; off > 0; off >>= 1)
            acc += __shfl_xor_sync(0xFFFFFFFFu, acc, off);
        if (lane == 0) s_red[warp] = acc;
        __syncthreads();
        if (tid == 0) {
            float s = 0.0f;
#pragma unroll
            for (int w = 0; w < 8; w++) s += s_red[w];
            out[0] = s / (float)G;
            g_count = 0;   // reset for next graph replay
        }
    }
}

extern "C" void kernel_launch(void* const* d_in, const int* in_sizes, int n_in,
                              void* d_out, int out_size) {
    const float* emb = (const float*)d_in[0];
    // d_in[1] = labels (arange(B)//8): grouping implicit in block->row map
    float* out = (float*)d_out;
    fused_kernel<<<G, 256>>>(emb, out);
}